// round 1
// baseline (speedup 1.0000x reference)
#include <cuda_runtime.h>
#include <cstdint>

#define B_      64
#define P_      576
#define D_      768
#define G_      64
#define NN      65
#define SZ      4225      // 65*65
#define LDA     66
#define STEPS_  8
#define FLOOR_  0.0001f
#define EPS_    0.0001f
#define DT_     0.1f
#define GAMMA_  0.1f

// Output layout offsets (flattened tuple, float32)
#define O_KEEP   0          // (64,577)
#define O_PATCH  36928      // (64,576)
#define O_GID    73792      // (64,576)
#define O_GS     110656     // (64,576)
#define O_DH     147520     // (64,9,65,65)
#define O_QH     2581120    // (64,8,65,65)
#define O_RT     4744320    // (64,64,64)
#define O_AUX    5006464    // 2 scalars

// Scratch (static device globals — no runtime allocation)
__device__ float g_nodes[B_*NN*D_];
__device__ float g_proj [B_*NN*D_];
__device__ float g_sq   [B_*NN];
__device__ float g_gf   [B_*G_];
__device__ float g_aux  [B_*2];

// ---------------------------------------------------------------------------
// Kernel A: group means + nodes assembly.  grid=(65,64), 256 threads
// ---------------------------------------------------------------------------
__global__ void k_group(const float* __restrict__ tokens,
                        const float* __restrict__ cls) {
    int n = blockIdx.x;      // node 0..64
    int b = blockIdx.y;
    int tid = threadIdx.x;
    float* dst = g_nodes + ((size_t)b*NN + n)*D_;
    if (n == 0) {
        for (int d = tid; d < D_; d += 256) dst[d] = cls[(size_t)b*D_ + d];
    } else {
        int g  = n - 1;
        int r0 = (g >> 3) * 3, c0 = (g & 7) * 3;
        for (int d = tid; d < D_; d += 256) {
            float s = 0.f;
            #pragma unroll
            for (int dr = 0; dr < 3; dr++)
                #pragma unroll
                for (int dc = 0; dc < 3; dc++) {
                    int p = (r0+dr)*24 + (c0+dc);
                    s += tokens[((size_t)b*P_ + p)*D_ + d];
                }
            dst[d] = s * (1.0f/9.0f);
        }
    }
}

// ---------------------------------------------------------------------------
// Kernel B: GEMM  proj[r,e] = sum_d nodes[r,d] * W[e,d]
//   M=4160, N=768, K=768.  Tiles 64x64x32, 256 threads, 4x4 microtile.
//   grid=(65,12)
// ---------------------------------------------------------------------------
__global__ void k_gemm(const float* __restrict__ Wm) {
    __shared__ float As[64][36];   // natural [m][k], padded
    __shared__ float Bs[32][68];   // transposed [k][n], padded
    const float* A = g_nodes;
    int tid = threadIdx.x;
    int tx = tid & 15, ty = tid >> 4;
    int m0 = blockIdx.x * 64, n0 = blockIdx.y * 64;
    float acc[4][4] = {};
    int r  = tid >> 3;           // 0..31
    int kc = (tid & 7) << 2;     // 0,4,...,28

    for (int k0 = 0; k0 < D_; k0 += 32) {
        #pragma unroll
        for (int h = 0; h < 2; h++) {
            float4 va = *(const float4*)(A  + (size_t)(m0 + r + 32*h)*D_ + k0 + kc);
            *(float4*)&As[r + 32*h][kc] = va;
            float4 vb = *(const float4*)(Wm + (size_t)(n0 + r + 32*h)*D_ + k0 + kc);
            Bs[kc+0][r+32*h] = vb.x;
            Bs[kc+1][r+32*h] = vb.y;
            Bs[kc+2][r+32*h] = vb.z;
            Bs[kc+3][r+32*h] = vb.w;
        }
        __syncthreads();
        #pragma unroll
        for (int kk = 0; kk < 32; kk++) {
            float a0 = As[ty*4+0][kk];
            float a1 = As[ty*4+1][kk];
            float a2 = As[ty*4+2][kk];
            float a3 = As[ty*4+3][kk];
            float4 bv = *(const float4*)&Bs[kk][tx*4];
            acc[0][0] += a0*bv.x; acc[0][1] += a0*bv.y; acc[0][2] += a0*bv.z; acc[0][3] += a0*bv.w;
            acc[1][0] += a1*bv.x; acc[1][1] += a1*bv.y; acc[1][2] += a1*bv.z; acc[1][3] += a1*bv.w;
            acc[2][0] += a2*bv.x; acc[2][1] += a2*bv.y; acc[2][2] += a2*bv.z; acc[2][3] += a2*bv.w;
            acc[3][0] += a3*bv.x; acc[3][1] += a3*bv.y; acc[3][2] += a3*bv.z; acc[3][3] += a3*bv.w;
        }
        __syncthreads();
    }
    #pragma unroll
    for (int i = 0; i < 4; i++)
        #pragma unroll
        for (int j = 0; j < 4; j++)
            g_proj[(size_t)(m0 + ty*4 + i)*D_ + n0 + tx*4 + j] = acc[i][j];
}

// ---------------------------------------------------------------------------
// Kernel C1: row normalization (4160 rows).  grid=4160, 256 threads
// ---------------------------------------------------------------------------
__global__ void k_norm() {
    int row = blockIdx.x, tid = threadIdx.x;
    float* pr = g_proj + (size_t)row*D_;
    float s = 0.f;
    for (int d = tid; d < D_; d += 256) { float v = pr[d]; s += v*v; }
    __shared__ float sred[256];
    sred[tid] = s; __syncthreads();
    for (int st = 128; st > 0; st >>= 1) {
        if (tid < st) sred[tid] += sred[tid+st];
        __syncthreads();
    }
    float s2  = sred[0];
    float inv = 1.0f / fmaxf(sqrtf(s2), 1e-12f);
    for (int d = tid; d < D_; d += 256) pr[d] *= inv;
    if (tid == 0) g_sq[row] = s2 * inv * inv;
}

// ---------------------------------------------------------------------------
// Kernel C2: per-batch Gram + C0 -> d_hist[b][0].  grid=64, 256 threads
// ---------------------------------------------------------------------------
__global__ void k_gram(float* __restrict__ out) {
    __shared__ float S[NN*133];
    __shared__ float ssq[NN];
    int b = blockIdx.x, tid = threadIdx.x;
    int tx = tid & 15, ty = tid >> 4;
    if (tid < NN) ssq[tid] = g_sq[b*NN + tid];
    const float* Pm = g_proj + (size_t)b*NN*D_;
    float acc[5][5] = {};
    int i4 = (ty + 64 < NN) ? (ty + 64) : 0;   // valid only for ty==0
    int j4 = (tx + 64 < NN) ? (tx + 64) : 0;   // valid only for tx==0
    for (int c0 = 0; c0 < D_; c0 += 128) {
        __syncthreads();
        for (int idx = tid; idx < NN*128; idx += 256) {
            int i = idx >> 7, dd = idx & 127;
            S[i*133 + dd] = Pm[(size_t)i*D_ + c0 + dd];
        }
        __syncthreads();
        for (int dd = 0; dd < 128; dd++) {
            float av[5], bv[5];
            av[0]=S[(ty   )*133+dd]; av[1]=S[(ty+16)*133+dd];
            av[2]=S[(ty+32)*133+dd]; av[3]=S[(ty+48)*133+dd]; av[4]=S[i4*133+dd];
            bv[0]=S[(tx   )*133+dd]; bv[1]=S[(tx+16)*133+dd];
            bv[2]=S[(tx+32)*133+dd]; bv[3]=S[(tx+48)*133+dd]; bv[4]=S[j4*133+dd];
            #pragma unroll
            for (int u = 0; u < 5; u++)
                #pragma unroll
                for (int v = 0; v < 5; v++)
                    acc[u][v] += av[u]*bv[v];
        }
    }
    __syncthreads();
    float* dh0 = out + O_DH + (size_t)b*9*SZ;
    #pragma unroll
    for (int u = 0; u < 5; u++) {
        int i = ty + 16*u; if (i >= NN) continue;
        #pragma unroll
        for (int v = 0; v < 5; v++) {
            int j = tx + 16*v; if (j >= NN) continue;
            float d2  = fmaxf(ssq[i] + ssq[j] - 2.0f*acc[u][v], 0.0f);
            float val = expf(-d2);                       // TAU = 1
            dh0[i*NN + j] = (i == j) ? 0.0f : fmaxf(val, FLOOR_);
        }
    }
}

// ---------------------------------------------------------------------------
// Kernel D: 8 Physarum steps per batch. Gauss-Jordan solve (diag-dominant,
// pivot-free is stable).  grid=64, 256 threads
// ---------------------------------------------------------------------------
__global__ void k_iter(float* __restrict__ out) {
    __shared__ float sC[NN*LDA];
    __shared__ float sA[NN*LDA];
    __shared__ float sp[NN];
    __shared__ float sred[256];
    int b = blockIdx.x, tid = threadIdx.x;
    float* dh = out + O_DH + (size_t)b*9*SZ;
    float* qh = out + O_QH + (size_t)b*8*SZ;

    for (int idx = tid; idx < SZ; idx += 256) {
        int i = idx/65, j = idx - i*65;
        sC[i*LDA + j] = dh[idx];
    }
    float st_acc = 0.f;
    int lane = tid & 31, w = tid >> 5;

    for (int step = 0; step < STEPS_; step++) {
        __syncthreads();
        // Build system A = deg*I - C + eps*I, augmented with source in col 65
        for (int idx = tid; idx < SZ; idx += 256) {
            int i = idx/65, j = idx - i*65;
            sA[i*LDA + j] = -sC[i*LDA + j];
        }
        __syncthreads();
        if (tid < NN) {
            float deg = 0.f;
            for (int j = 0; j < NN; j++) deg += sC[tid*LDA + j];
            sA[tid*LDA + tid] = deg + EPS_;
            sA[tid*LDA + NN]  = (tid == 0) ? 1.0f : (-1.0f/64.0f);
        }
        __syncthreads();
        // Gauss-Jordan (full elimination; no backsub needed)
        for (int k = 0; k < NN; k++) {
            float pinv = 1.0f / sA[k*LDA + k];
            for (int i = w; i < NN; i += 8) {
                if (i != k) {
                    float l = sA[i*LDA + k] * pinv;
                    for (int j = k+1+lane; j <= NN; j += 32)
                        sA[i*LDA + j] -= l * sA[k*LDA + j];
                }
            }
            __syncthreads();
        }
        if (tid < NN) sp[tid] = sA[tid*LDA + NN] / sA[tid*LDA + tid];
        __syncthreads();
        // Flow, q_hist, conductance update (pre-symmetrize into sA)
        for (int idx = tid; idx < SZ; idx += 256) {
            int i = idx/65, j = idx - i*65;
            float c  = sC[i*LDA + j];
            float fl = c * (sp[i] - sp[j]);
            qh[(size_t)step*SZ + idx] = fl;
            float r = fabsf(fl);            // MU = 1
            r = r / (1.0f + r);
            float tmp = c + DT_*(r - GAMMA_*c);
            sA[i*LDA + j] = (i == j) ? 0.f : fmaxf(tmp, FLOOR_);
        }
        if (step == STEPS_-1 && tid >= 1 && tid < NN) {
            // group_flow: |flow| row-sums of last step (rows 1..64)
            float s = 0.f, pi = sp[tid];
            for (int j = 0; j < NN; j++)
                s += fabsf(sC[tid*LDA + j] * (pi - sp[j]));
            g_gf[b*G_ + tid - 1] = s;
        }
        __syncthreads();
        // Symmetrize, floor, write d_hist, accumulate |delta|
        for (int idx = tid; idx < SZ; idx += 256) {
            int i = idx/65, j = idx - i*65;
            float nv = (i == j) ? 0.f
                     : fmaxf(0.5f*(sA[i*LDA + j] + sA[j*LDA + i]), FLOOR_);
            st_acc += fabsf(nv - sC[i*LDA + j]);
            sC[i*LDA + j] = nv;
            dh[(size_t)(step+1)*SZ + idx] = nv;
        }
    }
    __syncthreads();
    // aux partials
    float sp_acc = 0.f;
    for (int idx = tid; idx < SZ; idx += 256) {
        int i = idx/65, j = idx - i*65;
        if (i >= 1 && j >= 1) sp_acc += sC[i*LDA + j];
    }
    sred[tid] = sp_acc; __syncthreads();
    for (int s = 128; s > 0; s >>= 1) { if (tid < s) sred[tid] += sred[tid+s]; __syncthreads(); }
    if (tid == 0) g_aux[2*b] = sred[0];
    __syncthreads();
    sred[tid] = st_acc; __syncthreads();
    for (int s = 128; s > 0; s >>= 1) { if (tid < s) sred[tid] += sred[tid+s]; __syncthreads(); }
    if (tid == 0) g_aux[2*b + 1] = sred[0];
}

// ---------------------------------------------------------------------------
// Kernel E: scores, exact stable top-288, masks, gid, routing.
// grid=64, 576 threads
// ---------------------------------------------------------------------------
__device__ __forceinline__ float redsum576(float v, float* sred) {
    int tid = threadIdx.x;
    sred[tid] = v; __syncthreads();
    if (tid < 64) sred[tid] += sred[tid + 512];
    __syncthreads();
    for (int s = 256; s > 0; s >>= 1) {
        if (tid < s) sred[tid] += sred[tid + s];
        __syncthreads();
    }
    float r = sred[0];
    __syncthreads();
    return r;
}

__global__ void k_score(const float* __restrict__ local,
                        float* __restrict__ out) {
    __shared__ float sred[576];
    __shared__ float sts[576];
    __shared__ float sgs[64];
    __shared__ float srow[64];
    int b = blockIdx.x, tid = threadIdx.x;

    // local_scores normalization (mean, std ddof=1, clip 1e-6)
    float lv  = local[(size_t)b*P_ + tid];
    float lm  = redsum576(lv, sred) / 576.0f;
    float lc  = lv - lm;
    float lvr = redsum576(lc*lc, sred) / 575.0f;
    float lsn = lc / fmaxf(sqrtf(lvr), 1e-6f);

    // group_flow normalization over 64 groups
    float gv  = (tid < 64) ? g_gf[b*G_ + tid] : 0.f;
    float gm  = redsum576(gv, sred) / 64.0f;
    float gc  = gv - gm;
    float gvr = redsum576((tid < 64) ? gc*gc : 0.f, sred) / 63.0f;
    if (tid < 64) sgs[tid] = gc / fmaxf(sqrtf(gvr), 1e-6f);
    __syncthreads();

    int row = tid / 24, col = tid % 24;
    int g   = (row/3)*8 + (col/3);
    float gs = sgs[g];
    float ts = 1.0f*gs + 0.5f*lsn;   // FLOW_W, LOCAL_W
    sts[tid] = ts;
    out[O_GID + (size_t)b*P_ + tid] = (float)g;
    out[O_GS  + (size_t)b*P_ + tid] = gs;
    __syncthreads();

    // exact stable rank (matches lax.top_k tie-by-index)
    int cnt = 0;
    for (int q = 0; q < P_; q++) {
        float v = sts[q];
        cnt += (v > ts) || (v == ts && q < tid);
    }
    float keep = (cnt < 288) ? 1.0f : 0.0f;
    out[O_PATCH + (size_t)b*P_ + tid]     = keep;
    out[O_KEEP  + (size_t)b*577 + 1 + tid] = keep;
    if (tid == 0) out[O_KEEP + (size_t)b*577] = 1.0f;

    // routing from final C (d_hist slice 8)
    const float* dh8 = out + O_DH + ((size_t)b*9 + 8)*SZ;
    if (tid < 64) {
        float s = 0.f;
        for (int j = 0; j < 64; j++) s += dh8[(tid+1)*NN + (j+1)];
        srow[tid] = fmaxf(s, 1e-6f);
    }
    __syncthreads();
    for (int idx = tid; idx < 4096; idx += 576) {
        int i = idx >> 6, j = idx & 63;
        out[O_RT + (size_t)b*4096 + idx] = dh8[(i+1)*NN + (j+1)] / srow[i];
    }
}

// ---------------------------------------------------------------------------
// Kernel F: aux scalars (fixed-order, deterministic)
// ---------------------------------------------------------------------------
__global__ void k_aux(float* __restrict__ out) {
    if (threadIdx.x == 0) {
        float s1 = 0.f, s2 = 0.f;
        for (int b = 0; b < B_; b++) { s1 += g_aux[2*b]; s2 += g_aux[2*b+1]; }
        out[O_AUX]     = s1 / 64.0f;   // aux_sparse
        out[O_AUX + 1] = s2 / 64.0f;   // aux_stable
    }
}

// ---------------------------------------------------------------------------
extern "C" void kernel_launch(void* const* d_in, const int* in_sizes, int n_in,
                              void* d_out, int out_size) {
    const float* tokens = (const float*)d_in[0];
    const float* cls    = (const float*)d_in[1];
    const float* Wm     = (const float*)d_in[2];
    const float* local  = (const float*)d_in[3];
    float* out = (float*)d_out;

    k_group<<<dim3(65, 64), 256>>>(tokens, cls);
    k_gemm <<<dim3(65, 12), 256>>>(Wm);
    k_norm <<<4160, 256>>>();
    k_gram <<<64, 256>>>(out);
    k_iter <<<64, 256>>>(out);
    k_score<<<64, 576>>>(local, out);
    k_aux  <<<1, 32>>>(out);
}

// round 2
// speedup vs baseline: 1.0629x; 1.0629x over previous
#include <cuda_runtime.h>
#include <cstdint>

#define B_      64
#define P_      576
#define D_      768
#define G_      64
#define NN      65
#define SZ      4225      // 65*65
#define LDA     66
#define STEPS_  8
#define FLOOR_  0.0001f
#define EPS_    0.0001f
#define DT_     0.1f
#define GAMMA_  0.1f

#define MPAD    4224      // 33*128, padded row count for GEMM tiles

// Output layout offsets (flattened tuple, float32)
#define O_KEEP   0          // (64,577)
#define O_PATCH  36928      // (64,576)
#define O_GID    73792      // (64,576)
#define O_GS     110656     // (64,576)
#define O_DH     147520     // (64,9,65,65)
#define O_QH     2581120    // (64,8,65,65)
#define O_RT     4744320    // (64,64,64)
#define O_AUX    5006464    // 2 scalars

// Scratch (static device globals — zero-initialized at load, never alloc'd)
__device__ float g_nodes[MPAD*D_];      // padded rows 4160..4223 stay zero
__device__ float g_proj [MPAD*D_];
__device__ float g_sq   [B_*NN];
__device__ float g_gf   [B_*G_];
__device__ float g_aux  [B_*2];
__device__ float g_gpart[6*B_*SZ];      // split-K gram partials

// Packed dual-fp32 FMA (FFMA2) — exact fp32, 2x FFMA throughput
#define FMA2(c, a, b) asm("fma.rn.f32x2 %0, %1, %2, %0;" : "+l"(c) : "l"(a), "l"(b))

// ---------------------------------------------------------------------------
// Kernel A: group means + nodes assembly.  grid=(65,64), 192 threads (float4)
// ---------------------------------------------------------------------------
__global__ void k_group(const float* __restrict__ tokens,
                        const float* __restrict__ cls) {
    int n = blockIdx.x;      // node 0..64
    int b = blockIdx.y;
    int tid = threadIdx.x;   // 0..191, one float4 each
    float4* dst = (float4*)(g_nodes + ((size_t)b*NN + n)*D_);
    if (n == 0) {
        const float4* src = (const float4*)(cls + (size_t)b*D_);
        dst[tid] = src[tid];
    } else {
        int g  = n - 1;
        int r0 = (g >> 3) * 3, c0 = (g & 7) * 3;
        const float4* base = (const float4*)(tokens + (size_t)b*P_*D_);
        float4 s = make_float4(0.f, 0.f, 0.f, 0.f);
        #pragma unroll
        for (int dr = 0; dr < 3; dr++)
            #pragma unroll
            for (int dc = 0; dc < 3; dc++) {
                float4 v = base[(size_t)((r0+dr)*24 + (c0+dc))*(D_/4) + tid];
                s.x += v.x; s.y += v.y; s.z += v.z; s.w += v.w;
            }
        const float inv9 = 1.0f/9.0f;
        s.x *= inv9; s.y *= inv9; s.z *= inv9; s.w *= inv9;
        dst[tid] = s;
    }
}

// ---------------------------------------------------------------------------
// Kernel B: GEMM  proj[r,e] = sum_d nodes[r,d] * W[e,d]   (FFMA2 path)
//   M=4224(pad), N=768, K=768. Tile 128x64x32, 256 threads, 8x4 microtile.
//   grid=(33,12)
// ---------------------------------------------------------------------------
__global__ void k_gemm(const float* __restrict__ Wm) {
    __shared__ float2 As2[128][33];   // A value duplicated into both halves
    __shared__ float  Bs[32][68];     // [k][n]
    int tid = threadIdx.x;
    int tx = tid & 15, ty = tid >> 4;       // tx: n (4 cols), ty: m (8 rows)
    int m0 = blockIdx.x * 128, n0 = blockIdx.y * 64;
    unsigned long long acc[8][2] = {};      // 8 m-rows x 2 f32x2 (4 n-cols)

    for (int k0 = 0; k0 < D_; k0 += 32) {
        #pragma unroll
        for (int h = 0; h < 4; h++) {       // A: 128x32 = 1024 float4-quads
            int idx = tid + h*256;          // 0..1023
            int row = idx >> 3, c4 = (idx & 7) << 2;
            float4 v = *(const float4*)(g_nodes + (size_t)(m0+row)*D_ + k0 + c4);
            As2[row][c4+0] = make_float2(v.x, v.x);
            As2[row][c4+1] = make_float2(v.y, v.y);
            As2[row][c4+2] = make_float2(v.z, v.z);
            As2[row][c4+3] = make_float2(v.w, v.w);
        }
        #pragma unroll
        for (int h = 0; h < 2; h++) {       // B: 64x32 floats, transpose
            int idx = tid + h*256;          // 0..511
            int row = idx >> 3, c4 = (idx & 7) << 2;
            float4 v = *(const float4*)(Wm + (size_t)(n0+row)*D_ + k0 + c4);
            Bs[c4+0][row] = v.x; Bs[c4+1][row] = v.y;
            Bs[c4+2][row] = v.z; Bs[c4+3][row] = v.w;
        }
        __syncthreads();
        #pragma unroll
        for (int kk = 0; kk < 32; kk++) {
            ulonglong2 bv = *(const ulonglong2*)&Bs[kk][tx*4];
            #pragma unroll
            for (int i = 0; i < 8; i++) {
                unsigned long long a = *(const unsigned long long*)&As2[ty*8+i][kk];
                FMA2(acc[i][0], a, bv.x);
                FMA2(acc[i][1], a, bv.y);
            }
        }
        __syncthreads();
    }
    #pragma unroll
    for (int i = 0; i < 8; i++) {
        float4 o;
        o.x = __uint_as_float((unsigned)(acc[i][0]));
        o.y = __uint_as_float((unsigned)(acc[i][0] >> 32));
        o.z = __uint_as_float((unsigned)(acc[i][1]));
        o.w = __uint_as_float((unsigned)(acc[i][1] >> 32));
        *(float4*)(g_proj + (size_t)(m0 + ty*8 + i)*D_ + n0 + tx*4) = o;
    }
}

// ---------------------------------------------------------------------------
// Kernel C1: row normalization (4160 real rows).  grid=4160, 256 threads
// ---------------------------------------------------------------------------
__global__ void k_norm() {
    int row = blockIdx.x, tid = threadIdx.x;
    float* pr = g_proj + (size_t)row*D_;
    float s = 0.f;
    for (int d = tid; d < D_; d += 256) { float v = pr[d]; s += v*v; }
    __shared__ float sred[256];
    sred[tid] = s; __syncthreads();
    for (int st = 128; st > 0; st >>= 1) {
        if (tid < st) sred[tid] += sred[tid+st];
        __syncthreads();
    }
    float s2  = sred[0];
    float inv = 1.0f / fmaxf(sqrtf(s2), 1e-12f);
    for (int d = tid; d < D_; d += 256) pr[d] *= inv;
    if (tid == 0) g_sq[row] = s2 * inv * inv;
}

// ---------------------------------------------------------------------------
// Kernel C2a: per-batch Gram partials, split-K over 6 chunks of 128.
// grid=(64,6), 256 threads
// ---------------------------------------------------------------------------
__global__ void k_gram_part() {
    __shared__ float S[NN*133];
    int b = blockIdx.x, ch = blockIdx.y, tid = threadIdx.x;
    int tx = tid & 15, ty = tid >> 4;
    const float* Pm = g_proj + (size_t)b*NN*D_ + ch*128;
    float acc[5][5] = {};
    int i4 = (ty + 64 < NN) ? (ty + 64) : 0;
    int j4 = (tx + 64 < NN) ? (tx + 64) : 0;

    for (int idx = tid; idx < NN*128; idx += 256) {
        int i = idx >> 7, dd = idx & 127;
        S[i*133 + dd] = Pm[(size_t)i*D_ + dd];
    }
    __syncthreads();
    for (int dd = 0; dd < 128; dd++) {
        float av[5], bv[5];
        av[0]=S[(ty   )*133+dd]; av[1]=S[(ty+16)*133+dd];
        av[2]=S[(ty+32)*133+dd]; av[3]=S[(ty+48)*133+dd]; av[4]=S[i4*133+dd];
        bv[0]=S[(tx   )*133+dd]; bv[1]=S[(tx+16)*133+dd];
        bv[2]=S[(tx+32)*133+dd]; bv[3]=S[(tx+48)*133+dd]; bv[4]=S[j4*133+dd];
        #pragma unroll
        for (int u = 0; u < 5; u++)
            #pragma unroll
            for (int v = 0; v < 5; v++)
                acc[u][v] += av[u]*bv[v];
    }
    float* dst = g_gpart + ((size_t)ch*B_ + b)*SZ;
    #pragma unroll
    for (int u = 0; u < 5; u++) {
        int i = ty + 16*u; if (i >= NN) continue;
        #pragma unroll
        for (int v = 0; v < 5; v++) {
            int j = tx + 16*v; if (j >= NN) continue;
            dst[i*NN + j] = acc[u][v];
        }
    }
}

// ---------------------------------------------------------------------------
// Kernel C2b: combine partials -> C0 -> d_hist[b][0].  grid=64, 256 threads
// ---------------------------------------------------------------------------
__global__ void k_gram_fin(float* __restrict__ out) {
    __shared__ float ssq[NN];
    int b = blockIdx.x, tid = threadIdx.x;
    if (tid < NN) ssq[tid] = g_sq[b*NN + tid];
    __syncthreads();
    float* dh0 = out + O_DH + (size_t)b*9*SZ;
    for (int idx = tid; idx < SZ; idx += 256) {
        float s = 0.f;
        #pragma unroll
        for (int ch = 0; ch < 6; ch++)
            s += g_gpart[((size_t)ch*B_ + b)*SZ + idx];
        int i = idx/65, j = idx - i*65;
        float d2  = fmaxf(ssq[i] + ssq[j] - 2.0f*s, 0.0f);
        float val = expf(-d2);                       // TAU = 1
        dh0[idx] = (i == j) ? 0.0f : fmaxf(val, FLOOR_);
    }
}

// ---------------------------------------------------------------------------
// Kernel D: 8 Physarum steps per batch. Gauss-Jordan solve (diag-dominant,
// pivot-free is stable).  grid=64, 256 threads
// ---------------------------------------------------------------------------
__global__ void k_iter(float* __restrict__ out) {
    __shared__ float sC[NN*LDA];
    __shared__ float sA[NN*LDA];
    __shared__ float sp[NN];
    __shared__ float sred[256];
    int b = blockIdx.x, tid = threadIdx.x;
    float* dh = out + O_DH + (size_t)b*9*SZ;
    float* qh = out + O_QH + (size_t)b*8*SZ;

    for (int idx = tid; idx < SZ; idx += 256) {
        int i = idx/65, j = idx - i*65;
        sC[i*LDA + j] = dh[idx];
    }
    float st_acc = 0.f;
    int lane = tid & 31, w = tid >> 5;

    for (int step = 0; step < STEPS_; step++) {
        __syncthreads();
        // Build system A = deg*I - C + eps*I, augmented with source in col 65
        for (int idx = tid; idx < SZ; idx += 256) {
            int i = idx/65, j = idx - i*65;
            sA[i*LDA + j] = -sC[i*LDA + j];
        }
        __syncthreads();
        if (tid < NN) {
            float deg = 0.f;
            for (int j = 0; j < NN; j++) deg += sC[tid*LDA + j];
            sA[tid*LDA + tid] = deg + EPS_;
            sA[tid*LDA + NN]  = (tid == 0) ? 1.0f : (-1.0f/64.0f);
        }
        __syncthreads();
        // Gauss-Jordan (full elimination; no backsub needed)
        for (int k = 0; k < NN; k++) {
            float pinv = 1.0f / sA[k*LDA + k];
            for (int i = w; i < NN; i += 8) {
                if (i != k) {
                    float l = sA[i*LDA + k] * pinv;
                    for (int j = k+1+lane; j <= NN; j += 32)
                        sA[i*LDA + j] -= l * sA[k*LDA + j];
                }
            }
            __syncthreads();
        }
        if (tid < NN) sp[tid] = sA[tid*LDA + NN] / sA[tid*LDA + tid];
        __syncthreads();
        // Flow, q_hist, conductance update (pre-symmetrize into sA)
        for (int idx = tid; idx < SZ; idx += 256) {
            int i = idx/65, j = idx - i*65;
            float c  = sC[i*LDA + j];
            float fl = c * (sp[i] - sp[j]);
            qh[(size_t)step*SZ + idx] = fl;
            float r = fabsf(fl);            // MU = 1
            r = r / (1.0f + r);
            float tmp = c + DT_*(r - GAMMA_*c);
            sA[i*LDA + j] = (i == j) ? 0.f : fmaxf(tmp, FLOOR_);
        }
        if (step == STEPS_-1 && tid >= 1 && tid < NN) {
            // group_flow: |flow| row-sums of last step (rows 1..64)
            float s = 0.f, pi = sp[tid];
            for (int j = 0; j < NN; j++)
                s += fabsf(sC[tid*LDA + j] * (pi - sp[j]));
            g_gf[b*G_ + tid - 1] = s;
        }
        __syncthreads();
        // Symmetrize, floor, write d_hist, accumulate |delta|
        for (int idx = tid; idx < SZ; idx += 256) {
            int i = idx/65, j = idx - i*65;
            float nv = (i == j) ? 0.f
                     : fmaxf(0.5f*(sA[i*LDA + j] + sA[j*LDA + i]), FLOOR_);
            st_acc += fabsf(nv - sC[i*LDA + j]);
            sC[i*LDA + j] = nv;
            dh[(size_t)(step+1)*SZ + idx] = nv;
        }
    }
    __syncthreads();
    // aux partials
    float sp_acc = 0.f;
    for (int idx = tid; idx < SZ; idx += 256) {
        int i = idx/65, j = idx - i*65;
        if (i >= 1 && j >= 1) sp_acc += sC[i*LDA + j];
    }
    sred[tid] = sp_acc; __syncthreads();
    for (int s = 128; s > 0; s >>= 1) { if (tid < s) sred[tid] += sred[tid+s]; __syncthreads(); }
    if (tid == 0) g_aux[2*b] = sred[0];
    __syncthreads();
    sred[tid] = st_acc; __syncthreads();
    for (int s = 128; s > 0; s >>= 1) { if (tid < s) sred[tid] += sred[tid+s]; __syncthreads(); }
    if (tid == 0) g_aux[2*b + 1] = sred[0];
}

// ---------------------------------------------------------------------------
// Kernel E: scores, exact stable top-288, masks, gid, routing.
// grid=64, 576 threads
// ---------------------------------------------------------------------------
__device__ __forceinline__ float redsum576(float v, float* sred) {
    int tid = threadIdx.x;
    sred[tid] = v; __syncthreads();
    if (tid < 64) sred[tid] += sred[tid + 512];
    __syncthreads();
    for (int s = 256; s > 0; s >>= 1) {
        if (tid < s) sred[tid] += sred[tid + s];
        __syncthreads();
    }
    float r = sred[0];
    __syncthreads();
    return r;
}

__global__ void k_score(const float* __restrict__ local,
                        float* __restrict__ out) {
    __shared__ float sred[576];
    __shared__ float sts[576];
    __shared__ float sgs[64];
    __shared__ float srow[64];
    int b = blockIdx.x, tid = threadIdx.x;

    // local_scores normalization (mean, std ddof=1, clip 1e-6)
    float lv  = local[(size_t)b*P_ + tid];
    float lm  = redsum576(lv, sred) / 576.0f;
    float lc  = lv - lm;
    float lvr = redsum576(lc*lc, sred) / 575.0f;
    float lsn = lc / fmaxf(sqrtf(lvr), 1e-6f);

    // group_flow normalization over 64 groups
    float gv  = (tid < 64) ? g_gf[b*G_ + tid] : 0.f;
    float gm  = redsum576(gv, sred) / 64.0f;
    float gc  = gv - gm;
    float gvr = redsum576((tid < 64) ? gc*gc : 0.f, sred) / 63.0f;
    if (tid < 64) sgs[tid] = gc / fmaxf(sqrtf(gvr), 1e-6f);
    __syncthreads();

    int row = tid / 24, col = tid % 24;
    int g   = (row/3)*8 + (col/3);
    float gs = sgs[g];
    float ts = 1.0f*gs + 0.5f*lsn;   // FLOW_W, LOCAL_W
    sts[tid] = ts;
    out[O_GID + (size_t)b*P_ + tid] = (float)g;
    out[O_GS  + (size_t)b*P_ + tid] = gs;
    __syncthreads();

    // exact stable rank (matches lax.top_k tie-by-index)
    int cnt = 0;
    for (int q = 0; q < P_; q++) {
        float v = sts[q];
        cnt += (v > ts) || (v == ts && q < tid);
    }
    float keep = (cnt < 288) ? 1.0f : 0.0f;
    out[O_PATCH + (size_t)b*P_ + tid]     = keep;
    out[O_KEEP  + (size_t)b*577 + 1 + tid] = keep;
    if (tid == 0) out[O_KEEP + (size_t)b*577] = 1.0f;

    // routing from final C (d_hist slice 8)
    const float* dh8 = out + O_DH + ((size_t)b*9 + 8)*SZ;
    if (tid < 64) {
        float s = 0.f;
        for (int j = 0; j < 64; j++) s += dh8[(tid+1)*NN + (j+1)];
        srow[tid] = fmaxf(s, 1e-6f);
    }
    __syncthreads();
    for (int idx = tid; idx < 4096; idx += 576) {
        int i = idx >> 6, j = idx & 63;
        out[O_RT + (size_t)b*4096 + idx] = dh8[(i+1)*NN + (j+1)] / srow[i];
    }
}

// ---------------------------------------------------------------------------
// Kernel F: aux scalars (fixed-order tree, deterministic). 64 threads
// ---------------------------------------------------------------------------
__global__ void k_aux(float* __restrict__ out) {
    __shared__ float s1[64], s2[64];
    int tid = threadIdx.x;
    s1[tid] = g_aux[2*tid];
    s2[tid] = g_aux[2*tid + 1];
    __syncthreads();
    for (int s = 32; s > 0; s >>= 1) {
        if (tid < s) { s1[tid] += s1[tid+s]; s2[tid] += s2[tid+s]; }
        __syncthreads();
    }
    if (tid == 0) {
        out[O_AUX]     = s1[0] / 64.0f;   // aux_sparse
        out[O_AUX + 1] = s2[0] / 64.0f;   // aux_stable
    }
}

// ---------------------------------------------------------------------------
extern "C" void kernel_launch(void* const* d_in, const int* in_sizes, int n_in,
                              void* d_out, int out_size) {
    const float* tokens = (const float*)d_in[0];
    const float* cls    = (const float*)d_in[1];
    const float* Wm     = (const float*)d_in[2];
    const float* local  = (const float*)d_in[3];
    float* out = (float*)d_out;

    k_group    <<<dim3(65, 64), 192>>>(tokens, cls);
    k_gemm     <<<dim3(33, 12), 256>>>(Wm);
    k_norm     <<<4160, 256>>>();
    k_gram_part<<<dim3(64, 6), 256>>>();
    k_gram_fin <<<64, 256>>>(out);
    k_iter     <<<64, 256>>>(out);
    k_score    <<<64, 576>>>(local, out);
    k_aux      <<<1, 64>>>(out);
}

// round 3
// speedup vs baseline: 1.1004x; 1.0353x over previous
#include <cuda_runtime.h>
#include <cstdint>

#define B_      64
#define P_      576
#define D_      768
#define G_      64
#define NN      65
#define SZ      4225      // 65*65
#define LDA     66
#define STEPS_  8
#define FLOOR_  0.0001f
#define EPS_    0.0001f
#define DT_     0.1f
#define GAMMA_  0.1f

#define MPAD    4224      // 66*64, padded row count for GEMM tiles

// Output layout offsets (flattened tuple, float32)
#define O_KEEP   0          // (64,577)
#define O_PATCH  36928      // (64,576)
#define O_GID    73792      // (64,576)
#define O_GS     110656     // (64,576)
#define O_DH     147520     // (64,9,65,65)
#define O_QH     2581120    // (64,8,65,65)
#define O_RT     4744320    // (64,64,64)
#define O_AUX    5006464    // 2 scalars

// Scratch (static device globals — zero-initialized at load, never alloc'd)
__device__ float g_nodes[MPAD*D_];      // padded rows 4160..4223 stay zero
__device__ float g_proj [MPAD*D_];
__device__ float g_sq   [B_*NN];
__device__ float g_gf   [B_*G_];
__device__ float g_aux  [B_*2];
__device__ float g_gpart[6*B_*SZ];      // split-K gram partials

// Packed dual-fp32 FMA (FFMA2) — exact fp32, 2x FFMA throughput
#define FMA2(c, a, b) asm("fma.rn.f32x2 %0, %1, %2, %0;" : "+l"(c) : "l"(a), "l"(b))
// Duplicate one fp32 into both halves of a b64 (register-side, ALU pipe)
#define PACK2(d, s)   asm("mov.b64 %0, {%1, %1};" : "=l"(d) : "f"(s))

// ---------------------------------------------------------------------------
// Kernel A1: group means (nodes 1..64).  grid=(64,64), 192 threads (float4)
// ---------------------------------------------------------------------------
__global__ void k_group(const float* __restrict__ tokens) {
    int g = blockIdx.x;      // group 0..63 -> node g+1
    int b = blockIdx.y;
    int tid = threadIdx.x;   // 0..191, one float4 each
    float4* dst = (float4*)(g_nodes + ((size_t)b*NN + g + 1)*D_);
    int r0 = (g >> 3) * 3, c0 = (g & 7) * 3;
    const float4* base = (const float4*)(tokens + (size_t)b*P_*D_);
    float4 s = make_float4(0.f, 0.f, 0.f, 0.f);
    #pragma unroll
    for (int dr = 0; dr < 3; dr++)
        #pragma unroll
        for (int dc = 0; dc < 3; dc++) {
            float4 v = base[(size_t)((r0+dr)*24 + (c0+dc))*(D_/4) + tid];
            s.x += v.x; s.y += v.y; s.z += v.z; s.w += v.w;
        }
    const float inv9 = 1.0f/9.0f;
    s.x *= inv9; s.y *= inv9; s.z *= inv9; s.w *= inv9;
    dst[tid] = s;
}

// ---------------------------------------------------------------------------
// Kernel A2: cls copy (node 0).  grid=64, 192 threads
// ---------------------------------------------------------------------------
__global__ void k_cls(const float* __restrict__ cls) {
    int b = blockIdx.x, tid = threadIdx.x;
    float4* dst = (float4*)(g_nodes + (size_t)b*NN*D_);
    dst[tid] = ((const float4*)(cls + (size_t)b*D_))[tid];
}

// ---------------------------------------------------------------------------
// Kernel A3: keep-mask cls column init.  grid=1, 64 threads
// ---------------------------------------------------------------------------
__global__ void k_init(float* __restrict__ out) {
    out[O_KEEP + (size_t)threadIdx.x*577] = 1.0f;
}

// ---------------------------------------------------------------------------
// Kernel B: GEMM  proj[r,e] = sum_d nodes[r,d] * W[e,d]   (FFMA2, LSU-balanced)
//   M=4224(pad), N=768, K=768. Tile 64x128x16, 128 threads, 16x4 microtile.
//   Warp-uniform m-rows -> A smem loads are pure broadcasts; A duplicated
//   into f32x2 in registers (mov.b64), not in smem.  grid=(66,6)
// ---------------------------------------------------------------------------
__global__ void __launch_bounds__(128, 3) k_gemm(const float* __restrict__ Wm) {
    __shared__ float As[64][20];     // [m][k], pad 20
    __shared__ float Bs[16][132];    // [k][n], pad 132
    int tid  = threadIdx.x;
    int lane = tid & 31, w = tid >> 5;         // 4 warps
    int m0 = blockIdx.x * 64, n0 = blockIdx.y * 128;

    unsigned long long acc[16][2] = {};        // 16 m-rows x (2 f32x2 = 4 n)

    // loader indices
    int a_row0 = tid >> 1,  a_c4 = (tid & 1) << 3;   // 2 float4 per row? no:
    // A chunk: 64 rows x 16 k = 256 float4; 2 per thread
    //   idx = tid, tid+128 ; row = idx>>2, c4 = (idx&3)<<2
    // B chunk: 128 rows x 16 k = 512 float4; 4 per thread (scatter-transpose)
    (void)a_row0; (void)a_c4;

    for (int k0 = 0; k0 < D_; k0 += 16) {
        // ---- load A ----
        #pragma unroll
        for (int h = 0; h < 2; h++) {
            int idx = tid + h*128;
            int row = idx >> 2, c4 = (idx & 3) << 2;
            float4 v = *(const float4*)(g_nodes + (size_t)(m0+row)*D_ + k0 + c4);
            *(float4*)&As[row][c4] = v;
        }
        // ---- load B (transpose scatter) ----
        #pragma unroll
        for (int h = 0; h < 4; h++) {
            int idx = tid + h*128;
            int row = idx >> 2, c4 = (idx & 3) << 2;
            float4 v = *(const float4*)(Wm + (size_t)(n0+row)*D_ + k0 + c4);
            Bs[c4+0][row] = v.x; Bs[c4+1][row] = v.y;
            Bs[c4+2][row] = v.z; Bs[c4+3][row] = v.w;
        }
        __syncthreads();
        // ---- compute ----
        #pragma unroll
        for (int kk2 = 0; kk2 < 8; kk2++) {
            float2 av[16];
            #pragma unroll
            for (int r = 0; r < 16; r++)
                av[r] = *(const float2*)&As[w*16 + r][kk2*2];   // broadcast
            #pragma unroll
            for (int e = 0; e < 2; e++) {
                int kk = kk2*2 + e;
                ulonglong2 bb = *(const ulonglong2*)&Bs[kk][lane*4];
                #pragma unroll
                for (int r = 0; r < 16; r++) {
                    unsigned long long a2;
                    PACK2(a2, e ? av[r].y : av[r].x);
                    FMA2(acc[r][0], a2, bb.x);
                    FMA2(acc[r][1], a2, bb.y);
                }
            }
        }
        __syncthreads();
    }
    #pragma unroll
    for (int r = 0; r < 16; r++) {
        float4 o;
        o.x = __uint_as_float((unsigned)(acc[r][0]));
        o.y = __uint_as_float((unsigned)(acc[r][0] >> 32));
        o.z = __uint_as_float((unsigned)(acc[r][1]));
        o.w = __uint_as_float((unsigned)(acc[r][1] >> 32));
        *(float4*)(g_proj + (size_t)(m0 + w*16 + r)*D_ + n0 + lane*4) = o;
    }
}

// ---------------------------------------------------------------------------
// Kernel C1: row normalization (4160 real rows).  grid=4160, 256 threads
// ---------------------------------------------------------------------------
__global__ void k_norm() {
    int row = blockIdx.x, tid = threadIdx.x;
    float* pr = g_proj + (size_t)row*D_;
    float s = 0.f;
    for (int d = tid; d < D_; d += 256) { float v = pr[d]; s += v*v; }
    __shared__ float sred[256];
    sred[tid] = s; __syncthreads();
    for (int st = 128; st > 0; st >>= 1) {
        if (tid < st) sred[tid] += sred[tid+st];
        __syncthreads();
    }
    float s2  = sred[0];
    float inv = 1.0f / fmaxf(sqrtf(s2), 1e-12f);
    for (int d = tid; d < D_; d += 256) pr[d] *= inv;
    if (tid == 0) g_sq[row] = s2 * inv * inv;
}

// ---------------------------------------------------------------------------
// Kernel C2a: per-batch Gram partials, split-K over 6 chunks of 128.
// grid=(64,6), 256 threads
// ---------------------------------------------------------------------------
__global__ void k_gram_part() {
    __shared__ float S[NN*133];
    int b = blockIdx.x, ch = blockIdx.y, tid = threadIdx.x;
    int tx = tid & 15, ty = tid >> 4;
    const float* Pm = g_proj + (size_t)b*NN*D_ + ch*128;
    float acc[5][5] = {};
    int i4 = (ty + 64 < NN) ? (ty + 64) : 0;
    int j4 = (tx + 64 < NN) ? (tx + 64) : 0;

    for (int idx = tid; idx < NN*128; idx += 256) {
        int i = idx >> 7, dd = idx & 127;
        S[i*133 + dd] = Pm[(size_t)i*D_ + dd];
    }
    __syncthreads();
    for (int dd = 0; dd < 128; dd++) {
        float av[5], bv[5];
        av[0]=S[(ty   )*133+dd]; av[1]=S[(ty+16)*133+dd];
        av[2]=S[(ty+32)*133+dd]; av[3]=S[(ty+48)*133+dd]; av[4]=S[i4*133+dd];
        bv[0]=S[(tx   )*133+dd]; bv[1]=S[(tx+16)*133+dd];
        bv[2]=S[(tx+32)*133+dd]; bv[3]=S[(tx+48)*133+dd]; bv[4]=S[j4*133+dd];
        #pragma unroll
        for (int u = 0; u < 5; u++)
            #pragma unroll
            for (int v = 0; v < 5; v++)
                acc[u][v] += av[u]*bv[v];
    }
    float* dst = g_gpart + ((size_t)ch*B_ + b)*SZ;
    #pragma unroll
    for (int u = 0; u < 5; u++) {
        int i = ty + 16*u; if (i >= NN) continue;
        #pragma unroll
        for (int v = 0; v < 5; v++) {
            int j = tx + 16*v; if (j >= NN) continue;
            dst[i*NN + j] = acc[u][v];
        }
    }
}

// ---------------------------------------------------------------------------
// Kernel C2b: combine partials -> C0 -> d_hist[b][0].  grid=64, 256 threads
// ---------------------------------------------------------------------------
__global__ void k_gram_fin(float* __restrict__ out) {
    __shared__ float ssq[NN];
    int b = blockIdx.x, tid = threadIdx.x;
    if (tid < NN) ssq[tid] = g_sq[b*NN + tid];
    __syncthreads();
    float* dh0 = out + O_DH + (size_t)b*9*SZ;
    for (int idx = tid; idx < SZ; idx += 256) {
        float s = 0.f;
        #pragma unroll
        for (int ch = 0; ch < 6; ch++)
            s += g_gpart[((size_t)ch*B_ + b)*SZ + idx];
        int i = idx/65, j = idx - i*65;
        float d2  = fmaxf(ssq[i] + ssq[j] - 2.0f*s, 0.0f);
        float val = expf(-d2);                       // TAU = 1
        dh0[idx] = (i == j) ? 0.0f : fmaxf(val, FLOOR_);
    }
}

// ---------------------------------------------------------------------------
// Kernel D: 8 Physarum steps per batch. Gauss-Jordan solve (diag-dominant,
// pivot-free is stable).  grid=64, 256 threads.  Pivot row cached in regs.
// ---------------------------------------------------------------------------
__global__ void k_iter(float* __restrict__ out) {
    __shared__ float sC[NN*LDA];
    __shared__ float sA[NN*LDA];
    __shared__ float sp[NN];
    __shared__ float sred[256];
    int b = blockIdx.x, tid = threadIdx.x;
    float* dh = out + O_DH + (size_t)b*9*SZ;
    float* qh = out + O_QH + (size_t)b*8*SZ;

    for (int idx = tid; idx < SZ; idx += 256) {
        int i = idx/65, j = idx - i*65;
        sC[i*LDA + j] = dh[idx];
    }
    float st_acc = 0.f;
    int lane = tid & 31, w = tid >> 5;

    for (int step = 0; step < STEPS_; step++) {
        __syncthreads();
        // Build system A = deg*I - C + eps*I, augmented with source in col 65
        for (int idx = tid; idx < SZ; idx += 256) {
            int i = idx/65, j = idx - i*65;
            sA[i*LDA + j] = -sC[i*LDA + j];
        }
        __syncthreads();
        if (tid < NN) {
            float deg = 0.f;
            for (int j = 0; j < NN; j++) deg += sC[tid*LDA + j];
            sA[tid*LDA + tid] = deg + EPS_;
            sA[tid*LDA + NN]  = (tid == 0) ? 1.0f : (-1.0f/64.0f);
        }
        __syncthreads();
        // Gauss-Jordan (full elimination; no backsub needed)
        for (int k = 0; k < NN; k++) {
            float pinv = 1.0f / sA[k*LDA + k];
            int j0 = k + 1 + lane;
            bool m0 = (j0      <= NN);
            bool m1 = (j0 + 32 <= NN);
            bool m2 = (j0 + 64 <= NN);
            float pr0 = m0 ? sA[k*LDA + j0]      : 0.f;
            float pr1 = m1 ? sA[k*LDA + j0 + 32] : 0.f;
            float pr2 = m2 ? sA[k*LDA + j0 + 64] : 0.f;
            for (int i = w; i < NN; i += 8) {
                if (i != k) {
                    float l = sA[i*LDA + k] * pinv;
                    if (m0) sA[i*LDA + j0]      -= l * pr0;
                    if (m1) sA[i*LDA + j0 + 32] -= l * pr1;
                    if (m2) sA[i*LDA + j0 + 64] -= l * pr2;
                }
            }
            __syncthreads();
        }
        if (tid < NN) sp[tid] = sA[tid*LDA + NN] / sA[tid*LDA + tid];
        __syncthreads();
        // Flow, q_hist, conductance update (pre-symmetrize into sA)
        for (int idx = tid; idx < SZ; idx += 256) {
            int i = idx/65, j = idx - i*65;
            float c  = sC[i*LDA + j];
            float fl = c * (sp[i] - sp[j]);
            qh[(size_t)step*SZ + idx] = fl;
            float r = fabsf(fl);            // MU = 1
            r = r / (1.0f + r);
            float tmp = c + DT_*(r - GAMMA_*c);
            sA[i*LDA + j] = (i == j) ? 0.f : fmaxf(tmp, FLOOR_);
        }
        if (step == STEPS_-1 && tid >= 1 && tid < NN) {
            // group_flow: |flow| row-sums of last step (rows 1..64)
            float s = 0.f, pi = sp[tid];
            for (int j = 0; j < NN; j++)
                s += fabsf(sC[tid*LDA + j] * (pi - sp[j]));
            g_gf[b*G_ + tid - 1] = s;
        }
        __syncthreads();
        // Symmetrize, floor, write d_hist, accumulate |delta|
        for (int idx = tid; idx < SZ; idx += 256) {
            int i = idx/65, j = idx - i*65;
            float nv = (i == j) ? 0.f
                     : fmaxf(0.5f*(sA[i*LDA + j] + sA[j*LDA + i]), FLOOR_);
            st_acc += fabsf(nv - sC[i*LDA + j]);
            sC[i*LDA + j] = nv;
            dh[(size_t)(step+1)*SZ + idx] = nv;
        }
    }
    __syncthreads();
    // aux partials
    float sp_acc = 0.f;
    for (int idx = tid; idx < SZ; idx += 256) {
        int i = idx/65, j = idx - i*65;
        if (i >= 1 && j >= 1) sp_acc += sC[i*LDA + j];
    }
    sred[tid] = sp_acc; __syncthreads();
    for (int s = 128; s > 0; s >>= 1) { if (tid < s) sred[tid] += sred[tid+s]; __syncthreads(); }
    if (tid == 0) g_aux[2*b] = sred[0];
    __syncthreads();
    sred[tid] = st_acc; __syncthreads();
    for (int s = 128; s > 0; s >>= 1) { if (tid < s) sred[tid] += sred[tid+s]; __syncthreads(); }
    if (tid == 0) g_aux[2*b + 1] = sred[0];
}

// ---------------------------------------------------------------------------
// Kernel E: scores, exact stable top-288, masks, gid, routing.
// grid=64, 576 threads
// ---------------------------------------------------------------------------
__device__ __forceinline__ float redsum576(float v, float* sred) {
    int tid = threadIdx.x;
    sred[tid] = v; __syncthreads();
    if (tid < 64) sred[tid] += sred[tid + 512];
    __syncthreads();
    for (int s = 256; s > 0; s >>= 1) {
        if (tid < s) sred[tid] += sred[tid + s];
        __syncthreads();
    }
    float r = sred[0];
    __syncthreads();
    return r;
}

__global__ void k_score(const float* __restrict__ local,
                        float* __restrict__ out) {
    __shared__ float sred[576];
    __shared__ float sts[576];
    __shared__ float sgs[64];
    __shared__ float srow[64];
    int b = blockIdx.x, tid = threadIdx.x;

    // local_scores normalization (mean, std ddof=1, clip 1e-6)
    float lv  = local[(size_t)b*P_ + tid];
    float lm  = redsum576(lv, sred) / 576.0f;
    float lc  = lv - lm;
    float lvr = redsum576(lc*lc, sred) / 575.0f;
    float lsn = lc / fmaxf(sqrtf(lvr), 1e-6f);

    // group_flow normalization over 64 groups
    float gv  = (tid < 64) ? g_gf[b*G_ + tid] : 0.f;
    float gm  = redsum576(gv, sred) / 64.0f;
    float gc  = gv - gm;
    float gvr = redsum576((tid < 64) ? gc*gc : 0.f, sred) / 63.0f;
    if (tid < 64) sgs[tid] = gc / fmaxf(sqrtf(gvr), 1e-6f);
    __syncthreads();

    int row = tid / 24, col = tid % 24;
    int g   = (row/3)*8 + (col/3);
    float gs = sgs[g];
    float ts = 1.0f*gs + 0.5f*lsn;   // FLOW_W, LOCAL_W
    sts[tid] = ts;
    out[O_GID + (size_t)b*P_ + tid] = (float)g;
    out[O_GS  + (size_t)b*P_ + tid] = gs;
    __syncthreads();

    // exact stable rank (matches lax.top_k tie-by-index)
    int cnt = 0;
    for (int q = 0; q < P_; q++) {
        float v = sts[q];
        cnt += (v > ts) || (v == ts && q < tid);
    }
    float keep = (cnt < 288) ? 1.0f : 0.0f;
    out[O_PATCH + (size_t)b*P_ + tid]      = keep;
    out[O_KEEP  + (size_t)b*577 + 1 + tid] = keep;

    // routing from final C (d_hist slice 8)
    const float* dh8 = out + O_DH + ((size_t)b*9 + 8)*SZ;
    if (tid < 64) {
        float s = 0.f;
        for (int j = 0; j < 64; j++) s += dh8[(tid+1)*NN + (j+1)];
        srow[tid] = fmaxf(s, 1e-6f);
    }
    __syncthreads();
    for (int idx = tid; idx < 4096; idx += 576) {
        int i = idx >> 6, j = idx & 63;
        out[O_RT + (size_t)b*4096 + idx] = dh8[(i+1)*NN + (j+1)] / srow[i];
    }
}

// ---------------------------------------------------------------------------
// Kernel F: aux scalars (fixed-order tree, deterministic). 64 threads
// ---------------------------------------------------------------------------
__global__ void k_aux(float* __restrict__ out) {
    __shared__ float s1[64], s2[64];
    int tid = threadIdx.x;
    s1[tid] = g_aux[2*tid];
    s2[tid] = g_aux[2*tid + 1];
    __syncthreads();
    for (int s = 32; s > 0; s >>= 1) {
        if (tid < s) { s1[tid] += s1[tid+s]; s2[tid] += s2[tid+s]; }
        __syncthreads();
    }
    if (tid == 0) {
        out[O_AUX]     = s1[0] / 64.0f;   // aux_sparse
        out[O_AUX + 1] = s2[0] / 64.0f;   // aux_stable
    }
}

// ---------------------------------------------------------------------------
extern "C" void kernel_launch(void* const* d_in, const int* in_sizes, int n_in,
                              void* d_out, int out_size) {
    const float* tokens = (const float*)d_in[0];
    const float* cls    = (const float*)d_in[1];
    const float* Wm     = (const float*)d_in[2];
    const float* local  = (const float*)d_in[3];
    float* out = (float*)d_out;

    k_group    <<<dim3(64, 64), 192>>>(tokens);   // launch 0
    k_cls      <<<64, 192>>>(cls);                // launch 1
    k_init     <<<1, 64>>>(out);                  // launch 2
    k_gemm     <<<dim3(66, 6), 128>>>(Wm);        // launch 3  <- ncu probe
    k_norm     <<<4160, 256>>>();
    k_gram_part<<<dim3(64, 6), 256>>>();
    k_gram_fin <<<64, 256>>>(out);
    k_iter     <<<64, 256>>>(out);
    k_score    <<<64, 576>>>(local, out);
    k_aux      <<<1, 64>>>(out);
}

// round 4
// speedup vs baseline: 2.0071x; 1.8239x over previous
#include <cuda_runtime.h>
#include <cstdint>

#define B_      64
#define P_      576
#define D_      768
#define G_      64
#define NN      65
#define SZ      4225      // 65*65
#define LDA     67        // odd: conflict-free column walks
#define STEPS_  8
#define FLOOR_  0.0001f
#define EPS_    0.0001f
#define DT_     0.1f
#define GAMMA_  0.1f

#define MPAD    4224      // 66*64, padded row count for GEMM tiles

// Output layout offsets (flattened tuple, float32)
#define O_KEEP   0          // (64,577)
#define O_PATCH  36928      // (64,576)
#define O_GID    73792      // (64,576)
#define O_GS     110656     // (64,576)
#define O_DH     147520     // (64,9,65,65)
#define O_QH     2581120    // (64,8,65,65)
#define O_RT     4744320    // (64,64,64)
#define O_AUX    5006464    // 2 scalars

// Scratch (static device globals — zero-initialized at load, never alloc'd)
__device__ float g_nodes[MPAD*D_];      // padded rows 4160..4223 stay zero
__device__ float g_proj [MPAD*D_];
__device__ float g_gf   [B_*G_];
__device__ float g_aux  [B_*2];
__device__ float g_gpart[6*B_*SZ];      // split-K gram partials (raw dot products)

// Packed dual-fp32 FMA (FFMA2) — exact fp32, 2x FFMA throughput
#define FMA2(c, a, b) asm("fma.rn.f32x2 %0, %1, %2, %0;" : "+l"(c) : "l"(a), "l"(b))
// Duplicate one fp32 into both halves of a b64 (register-side, ALU pipe)
#define PACK2(d, s)   asm("mov.b64 %0, {%1, %1};" : "=l"(d) : "f"(s))

// ---------------------------------------------------------------------------
// Kernel A: group means + cls + keep-col init.  grid=(65,64), 192 threads
// ---------------------------------------------------------------------------
__global__ void k_group(const float* __restrict__ tokens,
                        const float* __restrict__ cls,
                        float* __restrict__ out) {
    int n = blockIdx.x;      // node 0..64
    int b = blockIdx.y;
    int tid = threadIdx.x;   // 0..191, one float4 each
    float4* dst = (float4*)(g_nodes + ((size_t)b*NN + n)*D_);
    if (n == 0) {
        dst[tid] = ((const float4*)(cls + (size_t)b*D_))[tid];
        if (tid == 0) out[O_KEEP + (size_t)b*577] = 1.0f;
    } else {
        int g  = n - 1;
        int r0 = (g >> 3) * 3, c0 = (g & 7) * 3;
        const float4* base = (const float4*)(tokens + (size_t)b*P_*D_);
        float4 s = make_float4(0.f, 0.f, 0.f, 0.f);
        #pragma unroll
        for (int dr = 0; dr < 3; dr++)
            #pragma unroll
            for (int dc = 0; dc < 3; dc++) {
                float4 v = base[(size_t)((r0+dr)*24 + (c0+dc))*(D_/4) + tid];
                s.x += v.x; s.y += v.y; s.z += v.z; s.w += v.w;
            }
        const float inv9 = 1.0f/9.0f;
        s.x *= inv9; s.y *= inv9; s.z *= inv9; s.w *= inv9;
        dst[tid] = s;
    }
}

// ---------------------------------------------------------------------------
// Kernel B: GEMM  proj[r,e] = sum_d nodes[r,d] * W[e,d]   (FFMA2)
//   Tile 64x128x16, 128 threads, 16x4 microtile.  grid=(66,6)
// ---------------------------------------------------------------------------
__global__ void __launch_bounds__(128, 3) k_gemm(const float* __restrict__ Wm) {
    __shared__ float As[64][20];     // [m][k], pad 20
    __shared__ float Bs[16][132];    // [k][n], pad 132
    int tid  = threadIdx.x;
    int lane = tid & 31, w = tid >> 5;         // 4 warps
    int m0 = blockIdx.x * 64, n0 = blockIdx.y * 128;

    unsigned long long acc[16][2] = {};        // 16 m-rows x (2 f32x2 = 4 n)

    for (int k0 = 0; k0 < D_; k0 += 16) {
        #pragma unroll
        for (int h = 0; h < 2; h++) {
            int idx = tid + h*128;
            int row = idx >> 2, c4 = (idx & 3) << 2;
            float4 v = *(const float4*)(g_nodes + (size_t)(m0+row)*D_ + k0 + c4);
            *(float4*)&As[row][c4] = v;
        }
        #pragma unroll
        for (int h = 0; h < 4; h++) {
            int idx = tid + h*128;
            int row = idx >> 2, c4 = (idx & 3) << 2;
            float4 v = *(const float4*)(Wm + (size_t)(n0+row)*D_ + k0 + c4);
            Bs[c4+0][row] = v.x; Bs[c4+1][row] = v.y;
            Bs[c4+2][row] = v.z; Bs[c4+3][row] = v.w;
        }
        __syncthreads();
        #pragma unroll
        for (int kk2 = 0; kk2 < 8; kk2++) {
            float2 av[16];
            #pragma unroll
            for (int r = 0; r < 16; r++)
                av[r] = *(const float2*)&As[w*16 + r][kk2*2];   // broadcast
            #pragma unroll
            for (int e = 0; e < 2; e++) {
                int kk = kk2*2 + e;
                ulonglong2 bb = *(const ulonglong2*)&Bs[kk][lane*4];
                #pragma unroll
                for (int r = 0; r < 16; r++) {
                    unsigned long long a2;
                    PACK2(a2, e ? av[r].y : av[r].x);
                    FMA2(acc[r][0], a2, bb.x);
                    FMA2(acc[r][1], a2, bb.y);
                }
            }
        }
        __syncthreads();
    }
    #pragma unroll
    for (int r = 0; r < 16; r++) {
        float4 o;
        o.x = __uint_as_float((unsigned)(acc[r][0]));
        o.y = __uint_as_float((unsigned)(acc[r][0] >> 32));
        o.z = __uint_as_float((unsigned)(acc[r][1]));
        o.w = __uint_as_float((unsigned)(acc[r][1] >> 32));
        *(float4*)(g_proj + (size_t)(m0 + w*16 + r)*D_ + n0 + lane*4) = o;
    }
}

// ---------------------------------------------------------------------------
// Kernel C: per-batch Gram partials on RAW proj, split-K 6 x 128.
// grid=(64,6), 256 threads
// ---------------------------------------------------------------------------
__global__ void k_gram_part() {
    __shared__ float S[NN*133];
    int b = blockIdx.x, ch = blockIdx.y, tid = threadIdx.x;
    int tx = tid & 15, ty = tid >> 4;
    const float* Pm = g_proj + (size_t)b*NN*D_ + ch*128;
    float acc[5][5] = {};
    int i4 = (ty + 64 < NN) ? (ty + 64) : 0;
    int j4 = (tx + 64 < NN) ? (tx + 64) : 0;

    for (int idx = tid; idx < NN*128; idx += 256) {
        int i = idx >> 7, dd = idx & 127;
        S[i*133 + dd] = Pm[(size_t)i*D_ + dd];
    }
    __syncthreads();
    for (int dd = 0; dd < 128; dd++) {
        float av[5], bv[5];
        av[0]=S[(ty   )*133+dd]; av[1]=S[(ty+16)*133+dd];
        av[2]=S[(ty+32)*133+dd]; av[3]=S[(ty+48)*133+dd]; av[4]=S[i4*133+dd];
        bv[0]=S[(tx   )*133+dd]; bv[1]=S[(tx+16)*133+dd];
        bv[2]=S[(tx+32)*133+dd]; bv[3]=S[(tx+48)*133+dd]; bv[4]=S[j4*133+dd];
        #pragma unroll
        for (int u = 0; u < 5; u++)
            #pragma unroll
            for (int v = 0; v < 5; v++)
                acc[u][v] += av[u]*bv[v];
    }
    float* dst = g_gpart + ((size_t)ch*B_ + b)*SZ;
    #pragma unroll
    for (int u = 0; u < 5; u++) {
        int i = ty + 16*u; if (i >= NN) continue;
        #pragma unroll
        for (int v = 0; v < 5; v++) {
            int j = tx + 16*v; if (j >= NN) continue;
            dst[i*NN + j] = acc[u][v];
        }
    }
}

// ---------------------------------------------------------------------------
// Kernel D: gram-finalize + 8 Physarum steps.  Blocked Gauss-Jordan (panel=8):
// warp0 factors panel in registers (shfl), all warps do rank-8 trailing update.
// grid=64, 256 threads.
// ---------------------------------------------------------------------------
__global__ void __launch_bounds__(256, 1) k_iter(float* __restrict__ out) {
    __shared__ float sC[NN*LDA];
    __shared__ float sA[NN*LDA];
    __shared__ float sL[NN*9];
    __shared__ float sU[8*64];
    __shared__ float sp[NN];
    __shared__ float sInv[NN];
    __shared__ float sSsq[NN];
    __shared__ float sred[256];
    int b = blockIdx.x, tid = threadIdx.x;
    int lane = tid & 31, w = tid >> 5;
    float* dh = out + O_DH + (size_t)b*9*SZ;
    float* qh = out + O_QH + (size_t)b*8*SZ;

    // ---- gram finalize: norms from partial diagonals ----
    if (tid < NN) {
        float sq = 0.f;
        #pragma unroll
        for (int ch = 0; ch < 6; ch++)
            sq += g_gpart[((size_t)ch*B_ + b)*SZ + tid*66];   // diag: tid*NN+tid
        float inv = 1.0f / fmaxf(sqrtf(sq), 1e-12f);
        sInv[tid] = inv;
        sSsq[tid] = sq * inv * inv;
    }
    __syncthreads();
    for (int idx = tid; idx < SZ; idx += 256) {
        float s = 0.f;
        #pragma unroll
        for (int ch = 0; ch < 6; ch++)
            s += g_gpart[((size_t)ch*B_ + b)*SZ + idx];
        int i = idx/65, j = idx - i*65;
        float dn = s * sInv[i] * sInv[j];
        float d2 = fmaxf(sSsq[i] + sSsq[j] - 2.0f*dn, 0.0f);
        float v  = (i == j) ? 0.0f : fmaxf(expf(-d2), FLOOR_);
        sC[i*LDA + j] = v;
        dh[idx] = v;
    }

    float st_acc = 0.f;

    for (int step = 0; step < STEPS_; step++) {
        __syncthreads();
        // ---- build A = deg*I - C + eps*I, aug col; row-per-warp + shfl ----
        for (int i = w; i < NN; i += 8) {
            float s = 0.f;
            int c0 = lane, c1 = lane+32, c2 = lane+64;
            float v0 = sC[i*LDA + c0]; s += v0; sA[i*LDA + c0] = -v0;
            float v1 = sC[i*LDA + c1]; s += v1; sA[i*LDA + c1] = -v1;
            if (c2 < NN) { float v2 = sC[i*LDA + c2]; s += v2; sA[i*LDA + c2] = -v2; }
            #pragma unroll
            for (int o = 16; o > 0; o >>= 1) s += __shfl_xor_sync(0xffffffffu, s, o);
            if (lane == 0) {
                sA[i*LDA + i]  = s + EPS_;
                sA[i*LDA + NN] = (i == 0) ? 1.0f : (-1.0f/64.0f);
            }
        }
        __syncthreads();
        // ---- blocked Gauss-Jordan ----
        for (int k0 = 0; k0 < NN; k0 += 8) {
            int PB = (NN - k0 < 8) ? (NN - k0) : 8;
            int T  = NN + 1 - (k0 + PB);       // trailing cols incl aug
            if (w == 0) {
                int i0 = lane, i1 = lane + 32, i2 = lane + 64;
                bool m1 = (i1 < NN), m2 = (i2 < NN);
                float a0[8], a1[8], a2[8];
                #pragma unroll
                for (int u = 0; u < 8; u++) {
                    a0[u] = (u < PB)       ? sA[i0*LDA + k0 + u] : 0.f;
                    a1[u] = (u < PB && m1) ? sA[i1*LDA + k0 + u] : 0.f;
                    a2[u] = (u < PB && m2) ? sA[i2*LDA + k0 + u] : 0.f;
                }
                #pragma unroll
                for (int t = 0; t < 8; t++) {
                    if (t >= PB) break;
                    int kk = k0 + t, rp = kk >> 5, lp = kk & 31;
                    float prow[8];
                    #pragma unroll
                    for (int u = 0; u < 8; u++) {
                        float cand = (rp == 0) ? a0[u] : (rp == 1) ? a1[u] : a2[u];
                        prow[u] = __shfl_sync(0xffffffffu, cand, lp);
                    }
                    float pinv = 1.0f / prow[t];
                    if (lane == lp) sA[kk*LDA + kk] = prow[t];   // at-pivot diag
                    float l0 = (i0 != kk)       ? a0[t]*pinv : 0.f;
                    float l1 = (m1 && i1 != kk) ? a1[t]*pinv : 0.f;
                    float l2 = (m2 && i2 != kk) ? a2[t]*pinv : 0.f;
                    sL[i0*9 + t] = l0;
                    if (m1) sL[i1*9 + t] = l1;
                    if (m2) sL[i2*9 + t] = l2;
                    #pragma unroll
                    for (int u = 0; u < 8; u++) if (u > t) {
                        a0[u] -= l0 * prow[u];
                        a1[u] -= l1 * prow[u];
                        a2[u] -= l2 * prow[u];
                    }
                }
                // ---- finalized pivot rows (Û) in registers ----
                float U[8][2];
                #pragma unroll
                for (int t = 0; t < 8; t++) {
                    if (t >= PB) break;
                    #pragma unroll
                    for (int s = 0; s < 2; s++) {
                        int c = lane + 32*s;
                        U[t][s] = (c < T) ? sA[(k0+t)*LDA + k0 + PB + c] : 0.f;
                    }
                    #pragma unroll
                    for (int tp = 0; tp < 8; tp++) if (tp < t) {
                        float lv = sL[(k0+t)*9 + tp];
                        U[t][0] -= lv * U[tp][0];
                        U[t][1] -= lv * U[tp][1];
                    }
                    #pragma unroll
                    for (int s = 0; s < 2; s++) {
                        int c = lane + 32*s;
                        if (c < T) sU[t*64 + c] = U[t][s];
                    }
                }
            }
            __syncthreads();
            // ---- rank-PB trailing update, all warps, U in registers ----
            float Ur[8][2];
            #pragma unroll
            for (int t = 0; t < 8; t++)
                #pragma unroll
                for (int s = 0; s < 2; s++) {
                    int c = lane + 32*s;
                    Ur[t][s] = (t < PB && c < T) ? sU[t*64 + c] : 0.f;
                }
            for (int i = w; i < NN; i += 8) {
                float lv[8];
                #pragma unroll
                for (int t = 0; t < 8; t++) lv[t] = (t < PB) ? sL[i*9 + t] : 0.f;
                #pragma unroll
                for (int s = 0; s < 2; s++) {
                    int c = lane + 32*s;
                    if (c < T) {
                        int j = k0 + PB + c;
                        float x = sA[i*LDA + j];
                        #pragma unroll
                        for (int t = 0; t < 8; t++) x -= lv[t] * Ur[t][s];
                        sA[i*LDA + j] = x;
                    }
                }
            }
            __syncthreads();
        }
        if (tid < NN) sp[tid] = sA[tid*LDA + NN] / sA[tid*LDA + tid];
        __syncthreads();
        // ---- flow, q_hist, conductance update (pre-symmetrize into sA) ----
        for (int idx = tid; idx < SZ; idx += 256) {
            int i = idx/65, j = idx - i*65;
            float c  = sC[i*LDA + j];
            float fl = c * (sp[i] - sp[j]);
            qh[(size_t)step*SZ + idx] = fl;
            float r = fabsf(fl);            // MU = 1
            r = r / (1.0f + r);
            float tmp = c + DT_*(r - GAMMA_*c);
            sA[i*LDA + j] = (i == j) ? 0.f : fmaxf(tmp, FLOOR_);
        }
        if (step == STEPS_-1) {
            // group_flow: |flow| row-sums, row-per-warp, conflict-free
            for (int i = w; i < NN; i += 8) {
                if (i >= 1) {
                    float s = 0.f, pi = sp[i];
                    for (int c = lane; c < NN; c += 32)
                        s += fabsf(sC[i*LDA + c] * (pi - sp[c]));
                    #pragma unroll
                    for (int o = 16; o > 0; o >>= 1) s += __shfl_xor_sync(0xffffffffu, s, o);
                    if (lane == 0) g_gf[b*G_ + i - 1] = s;
                }
            }
        }
        __syncthreads();
        // ---- symmetrize, floor, write d_hist, accumulate |delta| ----
        for (int idx = tid; idx < SZ; idx += 256) {
            int i = idx/65, j = idx - i*65;
            float nv = (i == j) ? 0.f
                     : fmaxf(0.5f*(sA[i*LDA + j] + sA[j*LDA + i]), FLOOR_);
            st_acc += fabsf(nv - sC[i*LDA + j]);
            sC[i*LDA + j] = nv;
            dh[(size_t)(step+1)*SZ + idx] = nv;
        }
    }
    __syncthreads();
    // ---- aux partials ----
    float sp_acc = 0.f;
    for (int idx = tid; idx < SZ; idx += 256) {
        int i = idx/65, j = idx - i*65;
        if (i >= 1 && j >= 1) sp_acc += sC[i*LDA + j];
    }
    sred[tid] = sp_acc; __syncthreads();
    for (int s = 128; s > 0; s >>= 1) { if (tid < s) sred[tid] += sred[tid+s]; __syncthreads(); }
    if (tid == 0) g_aux[2*b] = sred[0];
    __syncthreads();
    sred[tid] = st_acc; __syncthreads();
    for (int s = 128; s > 0; s >>= 1) { if (tid < s) sred[tid] += sred[tid+s]; __syncthreads(); }
    if (tid == 0) g_aux[2*b + 1] = sred[0];
}

// ---------------------------------------------------------------------------
// Kernel E: scores, exact stable top-288, masks, gid, routing.
// grid=64, 576 threads
// ---------------------------------------------------------------------------
__device__ __forceinline__ float redsum576(float v, float* sred) {
    int tid = threadIdx.x;
    sred[tid] = v; __syncthreads();
    if (tid < 64) sred[tid] += sred[tid + 512];
    __syncthreads();
    for (int s = 256; s > 0; s >>= 1) {
        if (tid < s) sred[tid] += sred[tid + s];
        __syncthreads();
    }
    float r = sred[0];
    __syncthreads();
    return r;
}

__global__ void k_score(const float* __restrict__ local,
                        float* __restrict__ out) {
    __shared__ float sred[576];
    __shared__ float sts[576];
    __shared__ float sgs[64];
    __shared__ float srow[64];
    int b = blockIdx.x, tid = threadIdx.x;

    float lv  = local[(size_t)b*P_ + tid];
    float lm  = redsum576(lv, sred) / 576.0f;
    float lc  = lv - lm;
    float lvr = redsum576(lc*lc, sred) / 575.0f;
    float lsn = lc / fmaxf(sqrtf(lvr), 1e-6f);

    float gv  = (tid < 64) ? g_gf[b*G_ + tid] : 0.f;
    float gm  = redsum576(gv, sred) / 64.0f;
    float gc  = gv - gm;
    float gvr = redsum576((tid < 64) ? gc*gc : 0.f, sred) / 63.0f;
    if (tid < 64) sgs[tid] = gc / fmaxf(sqrtf(gvr), 1e-6f);
    __syncthreads();

    int row = tid / 24, col = tid % 24;
    int g   = (row/3)*8 + (col/3);
    float gs = sgs[g];
    float ts = 1.0f*gs + 0.5f*lsn;
    sts[tid] = ts;
    out[O_GID + (size_t)b*P_ + tid] = (float)g;
    out[O_GS  + (size_t)b*P_ + tid] = gs;
    __syncthreads();

    int cnt = 0;
    for (int q = 0; q < P_; q++) {
        float v = sts[q];
        cnt += (v > ts) || (v == ts && q < tid);
    }
    float keep = (cnt < 288) ? 1.0f : 0.0f;
    out[O_PATCH + (size_t)b*P_ + tid]      = keep;
    out[O_KEEP  + (size_t)b*577 + 1 + tid] = keep;

    const float* dh8 = out + O_DH + ((size_t)b*9 + 8)*SZ;
    if (tid < 64) {
        float s = 0.f;
        for (int j = 0; j < 64; j++) s += dh8[(tid+1)*NN + (j+1)];
        srow[tid] = fmaxf(s, 1e-6f);
    }
    __syncthreads();
    for (int idx = tid; idx < 4096; idx += 576) {
        int i = idx >> 6, j = idx & 63;
        out[O_RT + (size_t)b*4096 + idx] = dh8[(i+1)*NN + (j+1)] / srow[i];
    }
}

// ---------------------------------------------------------------------------
// Kernel F: aux scalars (fixed-order tree, deterministic). 64 threads
// ---------------------------------------------------------------------------
__global__ void k_aux(float* __restrict__ out) {
    __shared__ float s1[64], s2[64];
    int tid = threadIdx.x;
    s1[tid] = g_aux[2*tid];
    s2[tid] = g_aux[2*tid + 1];
    __syncthreads();
    for (int s = 32; s > 0; s >>= 1) {
        if (tid < s) { s1[tid] += s1[tid+s]; s2[tid] += s2[tid+s]; }
        __syncthreads();
    }
    if (tid == 0) {
        out[O_AUX]     = s1[0] / 64.0f;   // aux_sparse
        out[O_AUX + 1] = s2[0] / 64.0f;   // aux_stable
    }
}

// ---------------------------------------------------------------------------
extern "C" void kernel_launch(void* const* d_in, const int* in_sizes, int n_in,
                              void* d_out, int out_size) {
    const float* tokens = (const float*)d_in[0];
    const float* cls    = (const float*)d_in[1];
    const float* Wm     = (const float*)d_in[2];
    const float* local  = (const float*)d_in[3];
    float* out = (float*)d_out;

    k_group    <<<dim3(65, 64), 192>>>(tokens, cls, out);  // launch 0
    k_gemm     <<<dim3(66, 6), 128>>>(Wm);                 // launch 1
    k_gram_part<<<dim3(64, 6), 256>>>();                   // launch 2
    k_iter     <<<64, 256>>>(out);                         // launch 3 <- probe
    k_score    <<<64, 576>>>(local, out);                  // launch 4
    k_aux      <<<1, 64>>>(out);                           // launch 5
}